// round 7
// baseline (speedup 1.0000x reference)
#include <cuda_runtime.h>

// FasterTensorProduct, factored form:
//   out[b,n1,n2,o] = sum_{s=0..3} sh[b,n1,s] * P[b,n2,s,o]
// where P[b,n2,s,:] = y(x_{b,n2}, e_s) is the bilinear map on the 4 sh basis
// vectors. Fully fused: each block computes P for its (b,n2) in smem, then
// fans out over half of the n1 range. Two blocks per (b,n2) (blockIdx.z)
// duplicate the cheap phase-1 to double block-level overlap of the
// store-latency-bound phase-2.
//
// Dims: M0E=64, M1O=32, M1E=32, M0O=16, IN_DIM=OUT_DIM=272, B=4, N=128.
// Weights (flat, row-major, each block scaled by 1/sqrt(rows)):
//   W0e at 0     : (96,64)
//   W1o at 6144  : (128,32)
//   W1e at 10240 : (80,32)
//   W0o at 12800 : (48,16)

#define B_DIM 4
#define N_DIM 128
#define IO_DIM 272

__global__ __launch_bounds__(272) void ftp_fused(
    const float* __restrict__ in_, const float4* __restrict__ sh4,
    const float* __restrict__ w, float4* __restrict__ outv)
{
    __shared__ float  xs[IO_DIM];     // input row for this (b, n2)
    __shared__ float4 shs[64];        // sh rows for this half of n1
    __shared__ float4 P4[IO_DIM];     // P4[o] = (P_s0[o], P_s1[o], P_s2[o], P_s3[o])

    const int tid  = threadIdx.x;
    const int n2   = blockIdx.x;
    const int b    = blockIdx.y;
    const int half = blockIdx.z;

    // ---- phase 0: cooperative loads ----
    const float* xrow = in_ + (size_t)(b * N_DIM + n2) * IO_DIM;
    xs[tid] = xrow[tid];
    if (tid < 64)
        shs[tid] = sh4[b * N_DIM + half * 64 + tid];
    __syncthreads();

    // ---- phase 1: compute P4[o] for o = tid ----
    const float inv2 = 0.7071067811865476f;   // 1/sqrt(2)
    const float inv3 = 0.5773502691896258f;   // 1/sqrt(3)

    float p0, p1, p2, p3;
    const int o = tid;

    if (o < 64) {
        // y0e: out0e = [x0e*sh0, (x1o . sh1)/sqrt3], W0e (96,64), 1/sqrt(96)
        const float s = 0.10206207261596575f;
        float a0 = 0.f;
        #pragma unroll
        for (int k = 0; k < 64; k++) a0 += xs[k] * w[k * 64 + o];
        float a1 = 0.f, a2 = 0.f, a3 = 0.f;
        #pragma unroll
        for (int m = 0; m < 32; m++) {
            float wv = w[(64 + m) * 64 + o];
            a1 += xs[64 + 3 * m + 0] * wv;
            a2 += xs[64 + 3 * m + 1] * wv;
            a3 += xs[64 + 3 * m + 2] * wv;
        }
        p0 = a0 * s;
        p1 = a1 * (s * inv3);
        p2 = a2 * (s * inv3);
        p3 = a3 * (s * inv3);
    } else if (o < 160) {
        // y1o: o = 64 + oo*3 + cp. W1o (128,32) at 6144, 1/sqrt(128)
        // rows: [0:64) x0e*sh1[c], [64:96) x1o*sh0, [96:128) cross(x1e,sh1)/sqrt2
        const float s  = 0.08838834764831845f;
        const int  t  = o - 64;
        const int  oo = t / 3;
        const int  cp = t - 3 * oo;
        const int  ca = (cp + 1) % 3;
        const int  cb = (cp + 2) % 3;
        const float* w1 = w + 6144;
        float A = 0.f, Bacc = 0.f, Ca = 0.f, Cb = 0.f;
        #pragma unroll
        for (int k = 0; k < 64; k++) Bacc += xs[k] * w1[k * 32 + oo];
        #pragma unroll
        for (int m = 0; m < 32; m++) {
            A += xs[64 + 3 * m + cp] * w1[(64 + m) * 32 + oo];
            float wv = w1[(96 + m) * 32 + oo];
            Ca += xs[160 + 3 * m + cb] * wv;   // cross(x1e, e_ca)[cp] = -x1e[cb]
            Cb += xs[160 + 3 * m + ca] * wv;   // cross(x1e, e_cb)[cp] = +x1e[ca]
        }
        p0 = A * s;
        float vB = Bacc * s;
        float vA = -Ca * (s * inv2);
        float vC =  Cb * (s * inv2);
        p1 = (cp == 0) ? vB : ((ca == 0) ? vA : vC);
        p2 = (cp == 1) ? vB : ((ca == 1) ? vA : vC);
        p3 = (cp == 2) ? vB : ((ca == 2) ? vA : vC);
    } else if (o < 256) {
        // y1e: o = 160 + oo*3 + cp. W1e (80,32) at 10240, 1/sqrt(80)
        // rows: [0:32) cross(x1o,sh1)/sqrt2, [32:64) x1e*sh0, [64:80) x0o*sh1[c]
        const float s  = 0.11180339887498949f;
        const int  t  = o - 160;
        const int  oo = t / 3;
        const int  cp = t - 3 * oo;
        const int  ca = (cp + 1) % 3;
        const int  cb = (cp + 2) % 3;
        const float* w2 = w + 10240;
        float A = 0.f, Bacc = 0.f, Ca = 0.f, Cb = 0.f;
        #pragma unroll
        for (int m = 0; m < 32; m++) {
            A += xs[160 + 3 * m + cp] * w2[(32 + m) * 32 + oo];
            float wv = w2[m * 32 + oo];
            Ca += xs[64 + 3 * m + cb] * wv;
            Cb += xs[64 + 3 * m + ca] * wv;
        }
        #pragma unroll
        for (int k = 0; k < 16; k++) Bacc += xs[256 + k] * w2[(64 + k) * 32 + oo];
        p0 = A * s;
        float vB = Bacc * s;
        float vA = -Ca * (s * inv2);
        float vC =  Cb * (s * inv2);
        p1 = (cp == 0) ? vB : ((ca == 0) ? vA : vC);
        p2 = (cp == 1) ? vB : ((ca == 1) ? vA : vC);
        p3 = (cp == 2) ? vB : ((ca == 2) ? vA : vC);
    } else {
        // y0o: o = 256 + oy. W0o (48,16) at 12800, 1/sqrt(48)
        const float s  = 0.14433756729740645f;
        const int  oy = o - 256;
        const float* w3 = w + 12800;
        float a0 = 0.f;
        #pragma unroll
        for (int k = 0; k < 16; k++) a0 += xs[256 + k] * w3[(32 + k) * 16 + oy];
        float a1 = 0.f, a2 = 0.f, a3 = 0.f;
        #pragma unroll
        for (int m = 0; m < 32; m++) {
            float wv = w3[m * 16 + oy];
            a1 += xs[160 + 3 * m + 0] * wv;
            a2 += xs[160 + 3 * m + 1] * wv;
            a3 += xs[160 + 3 * m + 2] * wv;
        }
        p0 = a0 * s;
        p1 = a1 * (s * inv3);
        p2 = a2 * (s * inv3);
        p3 = a3 * (s * inv3);
    }

    P4[o] = make_float4(p0, p1, p2, p3);
    __syncthreads();

    // ---- phase 2: fan-out over this half of n1 (DRAM-write bound) ----
    const int o4 = tid % 68;   // which float4 of the 272-wide output row
    const int g  = tid / 68;   // 0..3
    const float4 q0 = P4[o4 * 4 + 0];
    const float4 q1 = P4[o4 * 4 + 1];
    const float4 q2 = P4[o4 * 4 + 2];
    const float4 q3 = P4[o4 * 4 + 3];

    // out float4 index: ((b*128 + n1)*128 + n2)*68 + o4, n1 = half*64 + g + 4*i
    size_t base = ((size_t)(b * N_DIM + half * 64 + g) * N_DIM + n2) * 68 + o4;
    const size_t stride = (size_t)4 * N_DIM * 68;

    #pragma unroll
    for (int i = 0; i < 16; i++) {
        float4 s4 = shs[g + 4 * i];
        float4 r;
        r.x = q0.x * s4.x + q0.y * s4.y + q0.z * s4.z + q0.w * s4.w;
        r.y = q1.x * s4.x + q1.y * s4.y + q1.z * s4.z + q1.w * s4.w;
        r.z = q2.x * s4.x + q2.y * s4.y + q2.z * s4.z + q2.w * s4.w;
        r.w = q3.x * s4.x + q3.y * s4.y + q3.z * s4.z + q3.w * s4.w;
        outv[base + (size_t)i * stride] = r;
    }
}

extern "C" void kernel_launch(void* const* d_in, const int* in_sizes, int n_in,
                              void* d_out, int out_size) {
    const float* in_ = nullptr;
    const float* sh  = nullptr;
    const float* w   = nullptr;
    for (int i = 0; i < n_in; i++) {
        if (in_sizes[i] == B_DIM * N_DIM * IO_DIM)      in_ = (const float*)d_in[i];
        else if (in_sizes[i] == B_DIM * N_DIM * 4)      sh  = (const float*)d_in[i];
        else if (in_sizes[i] == 13568)                  w   = (const float*)d_in[i];
    }
    if (!in_) in_ = (const float*)d_in[0];
    if (!sh)  sh  = (const float*)d_in[1];
    if (!w)   w   = (const float*)d_in[2];

    dim3 grid(N_DIM, B_DIM, 2);
    ftp_fused<<<grid, 272>>>(in_, (const float4*)sh, w, (float4*)d_out);
}

// round 10
// speedup vs baseline: 1.0828x; 1.0828x over previous
#include <cuda_runtime.h>

// FasterTensorProduct, factored form:
//   out[b,n1,n2,o] = sum_{s=0..3} sh[b,n1,s] * P[b,n2,s,o]
// where P[b,n2,s,:] = y(x_{b,n2}, e_s) is the bilinear map on the 4 sh basis
// vectors. One block per (b,n2): 544 threads. Phase 1 (272 threads) computes
// P into smem in struct-of-arrays layout Ps[s][o] (conflict-free for both
// phases). Phase 2 (all 544 threads) fans out over all 128 n1 rows.
// Weights (54 KB) are staged into dynamic smem with coalesced float4 loads.
//
// Dims: M0E=64, M1O=32, M1E=32, M0O=16, IN_DIM=OUT_DIM=272, B=4, N=128.
// Weights (flat, row-major, each block scaled by 1/sqrt(rows)):
//   W0e at 0     : (96,64)
//   W1o at 6144  : (128,32)
//   W1e at 10240 : (80,32)
//   W0o at 12800 : (48,16)

#define B_DIM 4
#define N_DIM 128
#define IO_DIM 272
#define W_NUMEL 13568
#define THREADS 544

// dynamic smem layout (bytes):
//   ws  @ 0      : 13568 floats = 54272
//   shs @ 54272  : 128 float4   = 2048
//   xs  @ 56320  : 272 floats   = 1088
//   Ps  @ 57408  : 4*272 floats = 4352
// total = 61760
#define SMEM_WS   0
#define SMEM_SHS  54272
#define SMEM_XS   56320
#define SMEM_PS   57408
#define SMEM_TOTAL 61760

__global__ __launch_bounds__(THREADS, 3) void ftp_fused2(
    const float* __restrict__ in_, const float4* __restrict__ sh4,
    const float* __restrict__ w, float4* __restrict__ outv)
{
    extern __shared__ char smem[];
    float*  ws  = reinterpret_cast<float*>(smem + SMEM_WS);
    float4* shs = reinterpret_cast<float4*>(smem + SMEM_SHS);
    float*  xs  = reinterpret_cast<float*>(smem + SMEM_XS);
    float*  Ps  = reinterpret_cast<float*>(smem + SMEM_PS);   // Ps[s*272 + o]

    const int tid = threadIdx.x;
    const int n2  = blockIdx.x;
    const int b   = blockIdx.y;

    // ---- phase 0: cooperative loads (coalesced) ----
    {
        const float4* w4 = reinterpret_cast<const float4*>(w);
        float4* ws4 = reinterpret_cast<float4*>(ws);
        #pragma unroll
        for (int i = tid; i < W_NUMEL / 4; i += THREADS)
            ws4[i] = w4[i];
        if (tid < N_DIM)
            shs[tid] = sh4[b * N_DIM + tid];
        if (tid < IO_DIM)
            xs[tid] = in_[(size_t)(b * N_DIM + n2) * IO_DIM + tid];
    }
    __syncthreads();

    // ---- phase 1: threads 0..271 compute P[s][o] for o = tid ----
    if (tid < IO_DIM) {
        const float inv2 = 0.7071067811865476f;   // 1/sqrt(2)
        const float inv3 = 0.5773502691896258f;   // 1/sqrt(3)

        float p0, p1, p2, p3;
        const int o = tid;

        if (o < 64) {
            // y0e: out0e = [x0e*sh0, (x1o . sh1)/sqrt3], W0e (96,64), 1/sqrt(96)
            const float s = 0.10206207261596575f;
            float a0 = 0.f;
            #pragma unroll
            for (int k = 0; k < 64; k++) a0 += xs[k] * ws[k * 64 + o];
            float a1 = 0.f, a2 = 0.f, a3 = 0.f;
            #pragma unroll
            for (int m = 0; m < 32; m++) {
                float wv = ws[(64 + m) * 64 + o];
                a1 += xs[64 + 3 * m + 0] * wv;
                a2 += xs[64 + 3 * m + 1] * wv;
                a3 += xs[64 + 3 * m + 2] * wv;
            }
            p0 = a0 * s;
            p1 = a1 * (s * inv3);
            p2 = a2 * (s * inv3);
            p3 = a3 * (s * inv3);
        } else if (o < 160) {
            // y1o: o = 64 + oo*3 + cp. W1o (128,32) at 6144, 1/sqrt(128)
            // rows: [0:64) x0e*sh1[c], [64:96) x1o*sh0, [96:128) cross(x1e,sh1)/sqrt2
            const float s  = 0.08838834764831845f;
            const int  t  = o - 64;
            const int  oo = t / 3;
            const int  cp = t - 3 * oo;
            const int  ca = (cp + 1) % 3;
            const int  cb = (cp + 2) % 3;
            const float* w1 = ws + 6144;
            float A = 0.f, Bacc = 0.f, Ca = 0.f, Cb = 0.f;
            #pragma unroll
            for (int k = 0; k < 64; k++) Bacc += xs[k] * w1[k * 32 + oo];
            #pragma unroll
            for (int m = 0; m < 32; m++) {
                A += xs[64 + 3 * m + cp] * w1[(64 + m) * 32 + oo];
                float wv = w1[(96 + m) * 32 + oo];
                Ca += xs[160 + 3 * m + cb] * wv;   // cross(x1e, e_ca)[cp] = -x1e[cb]
                Cb += xs[160 + 3 * m + ca] * wv;   // cross(x1e, e_cb)[cp] = +x1e[ca]
            }
            p0 = A * s;
            float vB = Bacc * s;
            float vA = -Ca * (s * inv2);
            float vC =  Cb * (s * inv2);
            p1 = (cp == 0) ? vB : ((ca == 0) ? vA : vC);
            p2 = (cp == 1) ? vB : ((ca == 1) ? vA : vC);
            p3 = (cp == 2) ? vB : ((ca == 2) ? vA : vC);
        } else if (o < 256) {
            // y1e: o = 160 + oo*3 + cp. W1e (80,32) at 10240, 1/sqrt(80)
            // rows: [0:32) cross(x1o,sh1)/sqrt2, [32:64) x1e*sh0, [64:80) x0o*sh1[c]
            const float s  = 0.11180339887498949f;
            const int  t  = o - 160;
            const int  oo = t / 3;
            const int  cp = t - 3 * oo;
            const int  ca = (cp + 1) % 3;
            const int  cb = (cp + 2) % 3;
            const float* w2 = ws + 10240;
            float A = 0.f, Bacc = 0.f, Ca = 0.f, Cb = 0.f;
            #pragma unroll
            for (int m = 0; m < 32; m++) {
                A += xs[160 + 3 * m + cp] * w2[(32 + m) * 32 + oo];
                float wv = w2[m * 32 + oo];
                Ca += xs[64 + 3 * m + cb] * wv;
                Cb += xs[64 + 3 * m + ca] * wv;
            }
            #pragma unroll
            for (int k = 0; k < 16; k++) Bacc += xs[256 + k] * w2[(64 + k) * 32 + oo];
            p0 = A * s;
            float vB = Bacc * s;
            float vA = -Ca * (s * inv2);
            float vC =  Cb * (s * inv2);
            p1 = (cp == 0) ? vB : ((ca == 0) ? vA : vC);
            p2 = (cp == 1) ? vB : ((ca == 1) ? vA : vC);
            p3 = (cp == 2) ? vB : ((ca == 2) ? vA : vC);
        } else {
            // y0o: o = 256 + oy. W0o (48,16) at 12800, 1/sqrt(48)
            const float s  = 0.14433756729740645f;
            const int  oy = o - 256;
            const float* w3 = ws + 12800;
            float a0 = 0.f;
            #pragma unroll
            for (int k = 0; k < 16; k++) a0 += xs[256 + k] * w3[(32 + k) * 16 + oy];
            float a1 = 0.f, a2 = 0.f, a3 = 0.f;
            #pragma unroll
            for (int m = 0; m < 32; m++) {
                float wv = w3[m * 16 + oy];
                a1 += xs[160 + 3 * m + 0] * wv;
                a2 += xs[160 + 3 * m + 1] * wv;
                a3 += xs[160 + 3 * m + 2] * wv;
            }
            p0 = a0 * s;
            p1 = a1 * (s * inv3);
            p2 = a2 * (s * inv3);
            p3 = a3 * (s * inv3);
        }

        // struct-of-arrays: stride-1 across lanes -> conflict-free STS.32
        Ps[0 * IO_DIM + o] = p0;
        Ps[1 * IO_DIM + o] = p1;
        Ps[2 * IO_DIM + o] = p2;
        Ps[3 * IO_DIM + o] = p3;
    }
    __syncthreads();

    // ---- phase 2: fan-out over all n1 (STG-issue bound) ----
    const int o4 = tid % 68;   // which float4 of the 272-wide output row
    const int g  = tid / 68;   // 0..7

    // v_s = P[s][4*o4 .. 4*o4+3]; consecutive-lane LDS.128, conflict-free
    const float4 v0 = *reinterpret_cast<const float4*>(Ps + 0 * IO_DIM + 4 * o4);
    const float4 v1 = *reinterpret_cast<const float4*>(Ps + 1 * IO_DIM + 4 * o4);
    const float4 v2 = *reinterpret_cast<const float4*>(Ps + 2 * IO_DIM + 4 * o4);
    const float4 v3 = *reinterpret_cast<const float4*>(Ps + 3 * IO_DIM + 4 * o4);

    // out float4 index: ((b*128 + n1)*128 + n2)*68 + o4, n1 = g + 8*i
    size_t base = ((size_t)(b * N_DIM + g) * N_DIM + n2) * 68 + o4;
    const size_t stride = (size_t)8 * N_DIM * 68;

    #pragma unroll
    for (int i = 0; i < 16; i++) {
        float4 s4 = shs[g + 8 * i];
        float4 r;
        r.x = s4.x * v0.x + s4.y * v1.x + s4.z * v2.x + s4.w * v3.x;
        r.y = s4.x * v0.y + s4.y * v1.y + s4.z * v2.y + s4.w * v3.y;
        r.z = s4.x * v0.z + s4.y * v1.z + s4.z * v2.z + s4.w * v3.z;
        r.w = s4.x * v0.w + s4.y * v1.w + s4.z * v2.w + s4.w * v3.w;
        outv[base + (size_t)i * stride] = r;
    }
}

extern "C" void kernel_launch(void* const* d_in, const int* in_sizes, int n_in,
                              void* d_out, int out_size) {
    const float* in_ = nullptr;
    const float* sh  = nullptr;
    const float* w   = nullptr;
    for (int i = 0; i < n_in; i++) {
        if (in_sizes[i] == B_DIM * N_DIM * IO_DIM)      in_ = (const float*)d_in[i];
        else if (in_sizes[i] == B_DIM * N_DIM * 4)      sh  = (const float*)d_in[i];
        else if (in_sizes[i] == W_NUMEL)                w   = (const float*)d_in[i];
    }
    if (!in_) in_ = (const float*)d_in[0];
    if (!sh)  sh  = (const float*)d_in[1];
    if (!w)   w   = (const float*)d_in[2];

    // >48KB dynamic smem requires the opt-in attribute (host-side, idempotent,
    // not a stream op -> safe under graph capture).
    cudaFuncSetAttribute(ftp_fused2,
                         cudaFuncAttributeMaxDynamicSharedMemorySize, SMEM_TOTAL);

    dim3 grid(N_DIM, B_DIM);
    ftp_fused2<<<grid, THREADS, SMEM_TOTAL>>>(in_, (const float4*)sh, w, (float4*)d_out);
}

// round 11
// speedup vs baseline: 1.1165x; 1.0311x over previous
#include <cuda_runtime.h>

// FasterTensorProduct, factored form:
//   out[b,n1,n2,o] = sum_{s=0..3} sh[b,n1,s] * P[b,n2,s,o]
// where P[b,n2,s,:] = y(x_{b,n2}, e_s) is the bilinear map on the 4 sh basis
// vectors.
//
// Kernel A (ftp_precompute4): 128 blocks x 272 threads; each block computes P
// for 4 consecutive n2 rows, each thread computing one output column o for all
// 4 rows, reusing every weight load 4x (quarters the chip-wide LDG count).
// Kernel B (ftp_fanout): pure write-bandwidth fan-out (proven 13.4us shape),
// with __stcs streaming stores.
//
// Dims: M0E=64, M1O=32, M1E=32, M0O=16, IN_DIM=OUT_DIM=272, B=4, N=128.
// Weights (flat, row-major, each block scaled by 1/sqrt(rows)):
//   W0e at 0     : (96,64)
//   W1o at 6144  : (128,32)
//   W1e at 10240 : (80,32)
//   W0o at 12800 : (48,16)

#define B_DIM 4
#define N_DIM 128
#define IO_DIM 272
#define W_NUMEL 13568

__device__ float4 g_Pbuf[B_DIM * N_DIM * IO_DIM];   // [b][n2][o] -> (P_s0..P_s3)

// ---------------------------------------------------------------------------
// Kernel A: compute P, 4 rows per block with 4x weight-load reuse
// grid = (32, 4), block = 272
// ---------------------------------------------------------------------------
__global__ __launch_bounds__(272) void ftp_precompute4(
    const float* __restrict__ in_, const float* __restrict__ w)
{
    __shared__ float xs[4 * IO_DIM];   // xs[r*272 + k]

    const int tid    = threadIdx.x;
    const int n2base = blockIdx.x * 4;
    const int b      = blockIdx.y;

    // 4 consecutive input rows are contiguous: 1088 floats = 272 float4
    {
        const float4* src = reinterpret_cast<const float4*>(
            in_ + (size_t)(b * N_DIM + n2base) * IO_DIM);
        reinterpret_cast<float4*>(xs)[tid] = src[tid];
    }
    __syncthreads();

    const float inv2 = 0.7071067811865476f;   // 1/sqrt(2)
    const float inv3 = 0.5773502691896258f;   // 1/sqrt(3)

    float p0[4], p1[4], p2[4], p3[4];
    const int o = tid;

    if (o < 64) {
        // y0e: out0e = [x0e*sh0, (x1o . sh1)/sqrt3], W0e (96,64), 1/sqrt(96)
        const float s = 0.10206207261596575f;
        float a0[4] = {0.f,0.f,0.f,0.f};
        float a1[4] = {0.f,0.f,0.f,0.f};
        float a2[4] = {0.f,0.f,0.f,0.f};
        float a3[4] = {0.f,0.f,0.f,0.f};
        #pragma unroll
        for (int k = 0; k < 64; k++) {
            float wv = w[k * 64 + o];
            #pragma unroll
            for (int r = 0; r < 4; r++) a0[r] += xs[r * IO_DIM + k] * wv;
        }
        #pragma unroll
        for (int m = 0; m < 32; m++) {
            float wv = w[(64 + m) * 64 + o];
            #pragma unroll
            for (int r = 0; r < 4; r++) {
                a1[r] += xs[r * IO_DIM + 64 + 3 * m + 0] * wv;
                a2[r] += xs[r * IO_DIM + 64 + 3 * m + 1] * wv;
                a3[r] += xs[r * IO_DIM + 64 + 3 * m + 2] * wv;
            }
        }
        #pragma unroll
        for (int r = 0; r < 4; r++) {
            p0[r] = a0[r] * s;
            p1[r] = a1[r] * (s * inv3);
            p2[r] = a2[r] * (s * inv3);
            p3[r] = a3[r] * (s * inv3);
        }
    } else if (o < 160) {
        // y1o: o = 64 + oo*3 + cp. W1o (128,32) at 6144, 1/sqrt(128)
        // rows: [0:64) x0e*sh1[c], [64:96) x1o*sh0, [96:128) cross(x1e,sh1)/sqrt2
        const float s  = 0.08838834764831845f;
        const int  t  = o - 64;
        const int  oo = t / 3;
        const int  cp = t - 3 * oo;
        const int  ca = (cp + 1) % 3;
        const int  cb = (cp + 2) % 3;
        const float* w1 = w + 6144;
        float A[4]  = {0.f,0.f,0.f,0.f};
        float Bc[4] = {0.f,0.f,0.f,0.f};
        float Ca[4] = {0.f,0.f,0.f,0.f};
        float Cb[4] = {0.f,0.f,0.f,0.f};
        #pragma unroll
        for (int k = 0; k < 64; k++) {
            float wv = w1[k * 32 + oo];
            #pragma unroll
            for (int r = 0; r < 4; r++) Bc[r] += xs[r * IO_DIM + k] * wv;
        }
        #pragma unroll
        for (int m = 0; m < 32; m++) {
            float wva = w1[(64 + m) * 32 + oo];
            float wvb = w1[(96 + m) * 32 + oo];
            #pragma unroll
            for (int r = 0; r < 4; r++) {
                A[r]  += xs[r * IO_DIM + 64 + 3 * m + cp] * wva;
                Ca[r] += xs[r * IO_DIM + 160 + 3 * m + cb] * wvb;  // cross(x1e,e_ca)[cp] = -x1e[cb]
                Cb[r] += xs[r * IO_DIM + 160 + 3 * m + ca] * wvb;  // cross(x1e,e_cb)[cp] = +x1e[ca]
            }
        }
        #pragma unroll
        for (int r = 0; r < 4; r++) {
            p0[r] = A[r] * s;
            float vB = Bc[r] * s;
            float vA = -Ca[r] * (s * inv2);
            float vC =  Cb[r] * (s * inv2);
            p1[r] = (cp == 0) ? vB : ((ca == 0) ? vA : vC);
            p2[r] = (cp == 1) ? vB : ((ca == 1) ? vA : vC);
            p3[r] = (cp == 2) ? vB : ((ca == 2) ? vA : vC);
        }
    } else if (o < 256) {
        // y1e: o = 160 + oo*3 + cp. W1e (80,32) at 10240, 1/sqrt(80)
        // rows: [0:32) cross(x1o,sh1)/sqrt2, [32:64) x1e*sh0, [64:80) x0o*sh1[c]
        const float s  = 0.11180339887498949f;
        const int  t  = o - 160;
        const int  oo = t / 3;
        const int  cp = t - 3 * oo;
        const int  ca = (cp + 1) % 3;
        const int  cb = (cp + 2) % 3;
        const float* w2 = w + 10240;
        float A[4]  = {0.f,0.f,0.f,0.f};
        float Bc[4] = {0.f,0.f,0.f,0.f};
        float Ca[4] = {0.f,0.f,0.f,0.f};
        float Cb[4] = {0.f,0.f,0.f,0.f};
        #pragma unroll
        for (int m = 0; m < 32; m++) {
            float wva = w2[(32 + m) * 32 + oo];
            float wvb = w2[m * 32 + oo];
            #pragma unroll
            for (int r = 0; r < 4; r++) {
                A[r]  += xs[r * IO_DIM + 160 + 3 * m + cp] * wva;
                Ca[r] += xs[r * IO_DIM + 64 + 3 * m + cb] * wvb;
                Cb[r] += xs[r * IO_DIM + 64 + 3 * m + ca] * wvb;
            }
        }
        #pragma unroll
        for (int k = 0; k < 16; k++) {
            float wv = w2[(64 + k) * 32 + oo];
            #pragma unroll
            for (int r = 0; r < 4; r++) Bc[r] += xs[r * IO_DIM + 256 + k] * wv;
        }
        #pragma unroll
        for (int r = 0; r < 4; r++) {
            p0[r] = A[r] * s;
            float vB = Bc[r] * s;
            float vA = -Ca[r] * (s * inv2);
            float vC =  Cb[r] * (s * inv2);
            p1[r] = (cp == 0) ? vB : ((ca == 0) ? vA : vC);
            p2[r] = (cp == 1) ? vB : ((ca == 1) ? vA : vC);
            p3[r] = (cp == 2) ? vB : ((ca == 2) ? vA : vC);
        }
    } else {
        // y0o: o = 256 + oy. W0o (48,16) at 12800, 1/sqrt(48)
        const float s  = 0.14433756729740645f;
        const int  oy = o - 256;
        const float* w3 = w + 12800;
        float a0[4] = {0.f,0.f,0.f,0.f};
        float a1[4] = {0.f,0.f,0.f,0.f};
        float a2[4] = {0.f,0.f,0.f,0.f};
        float a3[4] = {0.f,0.f,0.f,0.f};
        #pragma unroll
        for (int k = 0; k < 16; k++) {
            float wv = w3[(32 + k) * 16 + oy];
            #pragma unroll
            for (int r = 0; r < 4; r++) a0[r] += xs[r * IO_DIM + 256 + k] * wv;
        }
        #pragma unroll
        for (int m = 0; m < 32; m++) {
            float wv = w3[m * 16 + oy];
            #pragma unroll
            for (int r = 0; r < 4; r++) {
                a1[r] += xs[r * IO_DIM + 160 + 3 * m + 0] * wv;
                a2[r] += xs[r * IO_DIM + 160 + 3 * m + 1] * wv;
                a3[r] += xs[r * IO_DIM + 160 + 3 * m + 2] * wv;
            }
        }
        #pragma unroll
        for (int r = 0; r < 4; r++) {
            p0[r] = a0[r] * s;
            p1[r] = a1[r] * (s * inv3);
            p2[r] = a2[r] * (s * inv3);
            p3[r] = a3[r] * (s * inv3);
        }
    }

    #pragma unroll
    for (int r = 0; r < 4; r++)
        g_Pbuf[(b * N_DIM + n2base + r) * IO_DIM + o] =
            make_float4(p0[r], p1[r], p2[r], p3[r]);
}

// ---------------------------------------------------------------------------
// Kernel B: fan-out   out[b,n1,n2,:] = sh[b,n1,:] . P[b,n2,:,:]
// grid = (n2=128, b=4, half=2); block = 272 threads (proven 13.4us shape)
// ---------------------------------------------------------------------------
__global__ __launch_bounds__(272) void ftp_fanout(
    const float4* __restrict__ sh4, float4* __restrict__ outv)
{
    __shared__ float4 shs[64];

    const int tid  = threadIdx.x;
    const int n2   = blockIdx.x;
    const int b    = blockIdx.y;
    const int half = blockIdx.z;

    if (tid < 64)
        shs[tid] = sh4[b * N_DIM + half * 64 + tid];
    __syncthreads();

    const int o4 = tid % 68;
    const int g  = tid / 68;

    const float4* __restrict__ Prow = g_Pbuf + (b * N_DIM + n2) * IO_DIM + o4 * 4;
    const float4 q0 = Prow[0];
    const float4 q1 = Prow[1];
    const float4 q2 = Prow[2];
    const float4 q3 = Prow[3];

    // output float4 index: ((b*128 + n1)*128 + n2)*68 + o4, n1 = half*64 + g + 4*i
    size_t base = ((size_t)(b * N_DIM + half * 64 + g) * N_DIM + n2) * 68 + o4;
    const size_t stride = (size_t)4 * N_DIM * 68;

    #pragma unroll
    for (int i = 0; i < 16; i++) {
        float4 s4 = shs[g + 4 * i];
        float4 r;
        r.x = q0.x * s4.x + q0.y * s4.y + q0.z * s4.z + q0.w * s4.w;
        r.y = q1.x * s4.x + q1.y * s4.y + q1.z * s4.z + q1.w * s4.w;
        r.z = q2.x * s4.x + q2.y * s4.y + q2.z * s4.z + q2.w * s4.w;
        r.w = q3.x * s4.x + q3.y * s4.y + q3.z * s4.z + q3.w * s4.w;
        __stcs(&outv[base + (size_t)i * stride], r);
    }
}

extern "C" void kernel_launch(void* const* d_in, const int* in_sizes, int n_in,
                              void* d_out, int out_size) {
    const float* in_ = nullptr;
    const float* sh  = nullptr;
    const float* w   = nullptr;
    for (int i = 0; i < n_in; i++) {
        if (in_sizes[i] == B_DIM * N_DIM * IO_DIM)      in_ = (const float*)d_in[i];
        else if (in_sizes[i] == B_DIM * N_DIM * 4)      sh  = (const float*)d_in[i];
        else if (in_sizes[i] == W_NUMEL)                w   = (const float*)d_in[i];
    }
    if (!in_) in_ = (const float*)d_in[0];
    if (!sh)  sh  = (const float*)d_in[1];
    if (!w)   w   = (const float*)d_in[2];

    dim3 gridA(N_DIM / 4, B_DIM);
    ftp_precompute4<<<gridA, 272>>>(in_, w);

    dim3 gridB(N_DIM, B_DIM, 2);
    ftp_fanout<<<gridB, 272>>>((const float4*)sh, (float4*)d_out);
}